// round 11
// baseline (speedup 1.0000x reference)
#include <cuda_runtime.h>
#include <math.h>

#define NB    512
#define NK    64
#define NC    2048
#define BDIM  128
#define SPLIT 2                       // CTAs per batch row
#define CHPB  (NC / SPLIT)            // 1024 channels per CTA
#define CPT   (CHPB / BDIM)           // 8 channels per thread
#define NPAIR (CPT / 2)               // 4 packed pairs per thread

typedef unsigned long long ull;

__device__ __forceinline__ ull pack2(float lo, float hi) {
    ull r;
    asm("mov.b64 %0, {%1, %2};" : "=l"(r) : "f"(lo), "f"(hi));
    return r;
}
__device__ __forceinline__ void unpack2(ull v, float& lo, float& hi) {
    asm("mov.b64 {%0, %1}, %2;" : "=f"(lo), "=f"(hi) : "l"(v));
}
__device__ __forceinline__ ull fma2(ull a, ull b, ull c) {
    ull r;
    asm("fma.rn.f32x2 %0, %1, %2, %3;" : "=l"(r) : "l"(a), "l"(b), "l"(c));
    return r;
}
__device__ __forceinline__ ull add2(ull a, ull b) {
    ull r;
    asm("add.rn.f32x2 %0, %1, %2;" : "=l"(r) : "l"(a), "l"(b));
    return r;
}
__device__ __forceinline__ float ex2a(float x) {
    float r;
    asm("ex2.approx.ftz.f32 %0, %1;" : "=f"(r) : "f"(x));
    return r;
}
__device__ __forceinline__ float lg2a(float x) {
    float r;
    asm("lg2.approx.ftz.f32 %0, %1;" : "=f"(r) : "f"(x));
    return r;
}

__global__ __launch_bounds__(BDIM, 8)
void mixture_kernel(const float* __restrict__ mo,
                    const float* __restrict__ X,
                    float* __restrict__ out) {
    // 64B coefficient record per k: [A B | C D | E F | pad] -> three LDS.128
    __shared__ __align__(16) ulonglong2 sCo[NK][4];

    const int b    = blockIdx.x / SPLIT;
    const int part = blockIdx.x % SPLIT;
    const int tid  = threadIdx.x;

    // --- per-(b,k) coefficient precompute (first 64 threads) ---
    if (tid < NK) {
        const float* p = mo + ((size_t)b * NK + tid) * 6;
        float w  = p[0];
        float m1 = p[1];
        float m2 = p[2];
        float s1 = p[3];
        float s2 = p[4];
        float r  = p[5];

        float omr2 = 1.0f - r * r;
        float inv  = 1.0f / omr2;
        float is1  = 1.0f / s1;
        float is2  = 1.0f / s2;

        const float L2E = 1.4426950408889634f;   // log2(e)
        float a  = -0.5f * inv * is1 * is1 * L2E;
        float bb =  r    * inv * is1 * is2 * L2E;
        float cc = -0.5f * inv * is2 * is2 * L2E;

        float d = -(2.0f * a  * m1 + bb * m2);
        float e = -(2.0f * cc * m2 + bb * m1);
        // fold weight/normalizer into exponent: W * 2^q == 2^(q + log2 W)
        float W = w * is1 * is2 * rsqrtf(omr2) * 0.15915494309189535f;
        float f = a * m1 * m1 + bb * m1 * m2 + cc * m2 * m2 + lg2a(W);

        sCo[tid][0] = make_ulonglong2(pack2(a,  a),  pack2(bb, bb));
        sCo[tid][1] = make_ulonglong2(pack2(cc, cc), pack2(d,  d));
        sCo[tid][2] = make_ulonglong2(pack2(e,  e),  pack2(f,  f));
    }
    __syncthreads();

    // --- per-thread packed channel state (4 pairs = 8 channels) ---
    const int base = part * CHPB;
    const float2* Xb = reinterpret_cast<const float2*>(X) + (size_t)b * NC + base;

    ull xx[NPAIR], yy[NPAIR], acc[NPAIR];
    #pragma unroll
    for (int p = 0; p < NPAIR; p++) {
        float2 v0 = Xb[tid + (2 * p)     * BDIM];
        float2 v1 = Xb[tid + (2 * p + 1) * BDIM];
        xx[p]  = pack2(v0.x, v1.x);
        yy[p]  = pack2(v0.y, v1.y);
        acc[p] = 0ull;
    }

    // --- two k's fused; quad->exp->acc interleaved per pair (low live regs) ---
    #pragma unroll 2
    for (int k2 = 0; k2 < NK; k2 += 2) {
        const ulonglong2 a01 = sCo[k2][0];
        const ulonglong2 a23 = sCo[k2][1];
        const ulonglong2 a45 = sCo[k2][2];
        const ulonglong2 b01 = sCo[k2 + 1][0];
        const ulonglong2 b23 = sCo[k2 + 1][1];
        const ulonglong2 b45 = sCo[k2 + 1][2];

        #pragma unroll
        for (int p = 0; p < NPAIR; p++) {
            ull ua = fma2(a01.x, xx[p], fma2(a01.y, yy[p], a23.y));
            ull va = fma2(a23.x, yy[p], a45.x);
            ull qa = fma2(ua, xx[p], fma2(va, yy[p], a45.y));

            ull ub = fma2(b01.x, xx[p], fma2(b01.y, yy[p], b23.y));
            ull vb = fma2(b23.x, yy[p], b45.x);
            ull qb = fma2(ub, xx[p], fma2(vb, yy[p], b45.y));

            float qa0, qa1, qb0, qb1;
            unpack2(qa, qa0, qa1);
            unpack2(qb, qb0, qb1);
            ull ea = pack2(ex2a(qa0), ex2a(qa1));
            ull eb = pack2(ex2a(qb0), ex2a(qb1));
            acc[p] = add2(add2(ea, eb), acc[p]);
        }
    }

    float* ob = out + (size_t)b * NC + base;
    #pragma unroll
    for (int p = 0; p < NPAIR; p++) {
        float a0, a1;
        unpack2(acc[p], a0, a1);
        ob[tid + (2 * p)     * BDIM] = a0;
        ob[tid + (2 * p + 1) * BDIM] = a1;
    }
}

extern "C" void kernel_launch(void* const* d_in, const int* in_sizes, int n_in,
                              void* d_out, int out_size) {
    const float* mo = (const float*)d_in[0];   // model_out: (512, 64, 6) f32
    const float* X  = (const float*)d_in[1];   // X:         (512, 2048, 2) f32
    float* out      = (float*)d_out;           // out:       (512, 2048) f32
    (void)in_sizes; (void)n_in; (void)out_size;

    mixture_kernel<<<NB * SPLIT, BDIM>>>(mo, X, out);
}

// round 12
// speedup vs baseline: 1.0959x; 1.0959x over previous
#include <cuda_runtime.h>
#include <math.h>

#define NB    512
#define NK    64
#define NC    2048
#define BDIM  128
#define SPLIT 2                       // CTAs per batch row
#define CHPB  (NC / SPLIT)            // 1024 channels per CTA
#define CPT   (CHPB / BDIM)           // 8 channels per thread
#define NPAIR (CPT / 2)               // 4 packed pairs per thread

typedef unsigned long long ull;

__device__ __forceinline__ ull pack2(float lo, float hi) {
    ull r;
    asm("mov.b64 %0, {%1, %2};" : "=l"(r) : "f"(lo), "f"(hi));
    return r;
}
__device__ __forceinline__ void unpack2(ull v, float& lo, float& hi) {
    asm("mov.b64 {%0, %1}, %2;" : "=f"(lo), "=f"(hi) : "l"(v));
}
__device__ __forceinline__ ull fma2(ull a, ull b, ull c) {
    ull r;
    asm("fma.rn.f32x2 %0, %1, %2, %3;" : "=l"(r) : "l"(a), "l"(b), "l"(c));
    return r;
}
__device__ __forceinline__ ull add2(ull a, ull b) {
    ull r;
    asm("add.rn.f32x2 %0, %1, %2;" : "=l"(r) : "l"(a), "l"(b));
    return r;
}
__device__ __forceinline__ float ex2a(float x) {
    float r;
    asm("ex2.approx.ftz.f32 %0, %1;" : "=f"(r) : "f"(x));
    return r;
}
__device__ __forceinline__ float lg2a(float x) {
    float r;
    asm("lg2.approx.ftz.f32 %0, %1;" : "=f"(r) : "f"(x));
    return r;
}

__global__ __launch_bounds__(BDIM, 7)
void mixture_kernel(const float* __restrict__ mo,
                    const float* __restrict__ X,
                    float* __restrict__ out) {
    // 64B coefficient record per k: [A B | C D | E F | pad] -> three LDS.128
    __shared__ __align__(16) ulonglong2 sCo[NK][4];

    const int b    = blockIdx.x / SPLIT;
    const int part = blockIdx.x % SPLIT;
    const int tid  = threadIdx.x;

    // --- per-(b,k) coefficient precompute (first 64 threads) ---
    if (tid < NK) {
        const float* p = mo + ((size_t)b * NK + tid) * 6;
        float w  = p[0];
        float m1 = p[1];
        float m2 = p[2];
        float s1 = p[3];
        float s2 = p[4];
        float r  = p[5];

        float omr2 = 1.0f - r * r;
        float inv  = 1.0f / omr2;
        float is1  = 1.0f / s1;
        float is2  = 1.0f / s2;

        const float L2E = 1.4426950408889634f;   // log2(e)
        float a  = -0.5f * inv * is1 * is1 * L2E;
        float bb =  r    * inv * is1 * is2 * L2E;
        float cc = -0.5f * inv * is2 * is2 * L2E;

        float d = -(2.0f * a  * m1 + bb * m2);
        float e = -(2.0f * cc * m2 + bb * m1);
        // fold weight/normalizer into exponent: W * 2^q == 2^(q + log2 W)
        float W = w * is1 * is2 * rsqrtf(omr2) * 0.15915494309189535f;
        float f = a * m1 * m1 + bb * m1 * m2 + cc * m2 * m2 + lg2a(W);

        sCo[tid][0] = make_ulonglong2(pack2(a,  a),  pack2(bb, bb));
        sCo[tid][1] = make_ulonglong2(pack2(cc, cc), pack2(d,  d));
        sCo[tid][2] = make_ulonglong2(pack2(e,  e),  pack2(f,  f));
    }
    __syncthreads();

    // --- per-thread packed channel state (4 pairs = 8 channels) ---
    const int base = part * CHPB;
    const float2* Xb = reinterpret_cast<const float2*>(X) + (size_t)b * NC + base;

    ull xx[NPAIR], yy[NPAIR], acca[NPAIR], accb[NPAIR];
    #pragma unroll
    for (int p = 0; p < NPAIR; p++) {
        float2 v0 = Xb[tid + (2 * p)     * BDIM];
        float2 v1 = Xb[tid + (2 * p + 1) * BDIM];
        xx[p]   = pack2(v0.x, v1.x);
        yy[p]   = pack2(v0.y, v1.y);
        acca[p] = 0ull;
        accb[p] = 0ull;
    }

    // --- two k's fused; independent accumulator per k-slot (no serial merge) ---
    #pragma unroll 8
    for (int k2 = 0; k2 < NK; k2 += 2) {
        const ulonglong2 a01 = sCo[k2][0];
        const ulonglong2 a23 = sCo[k2][1];
        const ulonglong2 a45 = sCo[k2][2];
        const ulonglong2 b01 = sCo[k2 + 1][0];
        const ulonglong2 b23 = sCo[k2 + 1][1];
        const ulonglong2 b45 = sCo[k2 + 1][2];

        ull qa[NPAIR], qb[NPAIR];
        #pragma unroll
        for (int p = 0; p < NPAIR; p++) {
            ull ua = fma2(a01.x, xx[p], fma2(a01.y, yy[p], a23.y));
            ull va = fma2(a23.x, yy[p], a45.x);
            qa[p]  = fma2(ua, xx[p], fma2(va, yy[p], a45.y));

            ull ub = fma2(b01.x, xx[p], fma2(b01.y, yy[p], b23.y));
            ull vb = fma2(b23.x, yy[p], b45.x);
            qb[p]  = fma2(ub, xx[p], fma2(vb, yy[p], b45.y));
        }
        #pragma unroll
        for (int p = 0; p < NPAIR; p++) {
            float qa0, qa1, qb0, qb1;
            unpack2(qa[p], qa0, qa1);
            unpack2(qb[p], qb0, qb1);
            ull ea = pack2(ex2a(qa0), ex2a(qa1));
            ull eb = pack2(ex2a(qb0), ex2a(qb1));
            acca[p] = add2(ea, acca[p]);
            accb[p] = add2(eb, accb[p]);
        }
    }

    float* ob = out + (size_t)b * NC + base;
    #pragma unroll
    for (int p = 0; p < NPAIR; p++) {
        ull s = add2(acca[p], accb[p]);
        float a0, a1;
        unpack2(s, a0, a1);
        ob[tid + (2 * p)     * BDIM] = a0;
        ob[tid + (2 * p + 1) * BDIM] = a1;
    }
}

extern "C" void kernel_launch(void* const* d_in, const int* in_sizes, int n_in,
                              void* d_out, int out_size) {
    const float* mo = (const float*)d_in[0];   // model_out: (512, 64, 6) f32
    const float* X  = (const float*)d_in[1];   // X:         (512, 2048, 2) f32
    float* out      = (float*)d_out;           // out:       (512, 2048) f32
    (void)in_sizes; (void)n_in; (void)out_size;

    mixture_kernel<<<NB * SPLIT, BDIM>>>(mo, X, out);
}